// round 11
// baseline (speedup 1.0000x reference)
#include <cuda_runtime.h>
#include <cstdint>
#include <math.h>

#define THREADS 256
#define DEPTH   2
#define BPB     16     // batches per block

// Scratch (zero-initialized at module load; counter reset by last block each call).
__device__ float g_partial[8192];
__device__ unsigned int g_count;

__device__ __forceinline__ float huber1(float x) {
    float a = fabsf(x);
    float q = fminf(a, 1.0f);
    return 0.5f * q * q + (a - q);
}

__device__ __forceinline__ uint32_t smem_u32(const void* p) {
    uint32_t a;
    asm("{ .reg .u64 tmp; cvta.to.shared.u64 tmp, %1; cvt.u32.u64 %0, tmp; }"
        : "=r"(a) : "l"(p));
    return a;
}

__device__ __forceinline__ void mbar_init(uint32_t mbar, uint32_t cnt) {
    asm volatile("mbarrier.init.shared.b64 [%0], %1;" :: "r"(mbar), "r"(cnt) : "memory");
}

__device__ __forceinline__ void mbar_expect_tx(uint32_t mbar, uint32_t bytes) {
    asm volatile("mbarrier.arrive.expect_tx.shared.b64 _, [%0], %1;"
                 :: "r"(mbar), "r"(bytes) : "memory");
}

__device__ __forceinline__ void mbar_wait(uint32_t mbar, uint32_t parity) {
    uint32_t done;
    asm volatile(
        "{\n\t"
        ".reg .pred p;\n\t"
        "mbarrier.try_wait.parity.acquire.cta.shared::cta.b64 p, [%1], %2;\n\t"
        "selp.b32 %0, 1, 0, p;\n\t"
        "}"
        : "=r"(done) : "r"(mbar), "r"(parity) : "memory");
    if (!done) {
        asm volatile(
            "{\n\t"
            ".reg .pred P1;\n\t"
            "WAIT_LOOP_%=:\n\t"
            "mbarrier.try_wait.parity.acquire.cta.shared::cta.b64 P1, [%0], %1, 0x989680;\n\t"
            "@P1 bra.uni WAIT_DONE_%=;\n\t"
            "bra.uni WAIT_LOOP_%=;\n\t"
            "WAIT_DONE_%=:\n\t"
            "}"
            :: "r"(mbar), "r"(parity) : "memory");
    }
}

__device__ __forceinline__ void bulk_g2s(uint32_t dst_smem, const void* src_gmem,
                                         uint32_t bytes, uint32_t mbar) {
    asm volatile(
        "cp.async.bulk.shared::cta.global.mbarrier::complete_tx::bytes [%0], [%1], %2, [%3];"
        :: "r"(dst_smem), "l"(src_gmem), "r"(bytes), "r"(mbar) : "memory");
}

__global__ __launch_bounds__(THREADS)
void loss_bulk_kernel(
    const float* __restrict__ mask_mean,     // (B,3)
    const float* __restrict__ pc,            // (B,3,N)
    const float* __restrict__ xd,            // (B,3,N)
    const float* __restrict__ center,        // (B,3)
    const float* __restrict__ size_res,      // (B,3)
    const float* __restrict__ head_res,      // (B,)
    const float* __restrict__ mean_sizes,    // (8,3)
    const int*   __restrict__ size_cls,      // (B,)
    const int*   __restrict__ head_cls,      // (B,)
    float* __restrict__ out,
    int Npts, int Bn, int nblocks)
{
    extern __shared__ char smem[];
    const int t    = threadIdx.x;
    const int lane = t & 31;
    const int wid  = t >> 5;

    const uint32_t xyBytes    = 8u  * (uint32_t)Npts;   // x+y rows (contiguous)
    const uint32_t xdBytes    = 12u * (uint32_t)Npts;   // all 3 xd rows
    const uint32_t stageBytes = xyBytes + xdBytes;

    // SMEM layout: [0..16) two mbarriers; [16..400) red[2][6][8]; data at 512.
    uint64_t* mbar64 = (uint64_t*)smem;
    float*    red    = (float*)(smem + 16);              // red[par*48 + acc*8 + warp]
    char*     data   = smem + 512;
    const uint32_t mbar0 = smem_u32(&mbar64[0]);

    const int b0      = blockIdx.x * BPB;
    const int nbLocal = min(BPB, Bn - b0);
    if (nbLocal > 0) {
        if (t == 0) {
            #pragma unroll
            for (int s = 0; s < DEPTH; s++) mbar_init(mbar0 + 8u * s, 1);
        }
        __syncthreads();

        // Prologue: issue first DEPTH batches.
        if (t == 0) {
            for (int i = 0; i < DEPTH && i < nbLocal; i++) {
                const int jb = b0 + i;
                const uint32_t mb = mbar0 + 8u * (i % DEPTH);
                const uint32_t dst = smem_u32(data + (uint32_t)(i % DEPTH) * stageBytes);
                mbar_expect_tx(mb, stageBytes);
                bulk_g2s(dst,           pc + (size_t)jb * 3 * Npts, xyBytes, mb);
                bulk_g2s(dst + xyBytes, xd + (size_t)jb * 3 * Npts, xdBytes, mb);
            }
        }

        const int nx4 = Npts >> 2;      // float4s per row
        const unsigned full = 0xffffffffu;

        for (int i = 0; i < nbLocal; i++) {
            const int b   = b0 + i;
            const int s   = i % DEPTH;
            const int par = (i / DEPTH) & 1;
            const int rpar = i & 1;

            mbar_wait(mbar0 + 8u * s, (uint32_t)par);

            const float4* sxy = (const float4*)(data + (uint32_t)s * stageBytes);
            const float4* sdl = (const float4*)(data + (uint32_t)s * stageBytes + xyBytes);

            float Sx = 0.f, Sy = 0.f, Sxx = 0.f, Syy = 0.f, Sxy = 0.f, Sq = 0.f;

            #pragma unroll 2
            for (int j = t; j < nx4; j += THREADS) {
                float4 x4 = sxy[j];
                float4 y4 = sxy[nx4 + j];
                Sx  += (x4.x + x4.y) + (x4.z + x4.w);
                Sy  += (y4.x + y4.y) + (y4.z + y4.w);
                Sxx += x4.x*x4.x + x4.y*x4.y + x4.z*x4.z + x4.w*x4.w;
                Syy += y4.x*y4.x + y4.y*y4.y + y4.z*y4.z + y4.w*y4.w;
                Sxy += x4.x*y4.x + x4.y*y4.y + x4.z*y4.z + x4.w*y4.w;
            }
            const int m4 = 3 * nx4;
            #pragma unroll 6
            for (int j = t; j < m4; j += THREADS) {
                float4 d = sdl[j];
                Sq += (d.x*d.x + d.y*d.y) + (d.z*d.z + d.w*d.w);
            }

            #pragma unroll
            for (int off = 16; off > 0; off >>= 1) {
                Sx  += __shfl_down_sync(full, Sx,  off);
                Sy  += __shfl_down_sync(full, Sy,  off);
                Sxx += __shfl_down_sync(full, Sxx, off);
                Syy += __shfl_down_sync(full, Syy, off);
                Sxy += __shfl_down_sync(full, Sxy, off);
                Sq  += __shfl_down_sync(full, Sq,  off);
            }
            if (lane == 0) {
                float* r = red + rpar * 48;
                r[0*8 + wid] = Sx;  r[1*8 + wid] = Sy;  r[2*8 + wid] = Sxx;
                r[3*8 + wid] = Syy; r[4*8 + wid] = Sxy; r[5*8 + wid] = Sq;
            }
            // One barrier: publishes red[] AND guarantees all stage reads done
            // before thread 0 re-issues a copy into this stage.
            __syncthreads();

            if (t == 0) {
                // Refill pipeline first (keep the bulk engine busy)...
                const int inext = i + DEPTH;
                if (inext < nbLocal) {
                    const int jb = b0 + inext;
                    const uint32_t mb = mbar0 + 8u * (inext % DEPTH);
                    const uint32_t dst = smem_u32(data + (uint32_t)(inext % DEPTH) * stageBytes);
                    mbar_expect_tx(mb, stageBytes);
                    bulk_g2s(dst,           pc + (size_t)jb * 3 * Npts, xyBytes, mb);
                    bulk_g2s(dst + xyBytes, xd + (size_t)jb * 3 * Npts, xdBytes, mb);
                }

                // ...then combine warp partials (fixed order) + scalar epilogue.
                const float* r = red + rpar * 48;
                float SxT = 0.f, SyT = 0.f, SxxT = 0.f, SyyT = 0.f, SxyT = 0.f, SqT = 0.f;
                #pragma unroll
                for (int w = 0; w < 8; w++) {
                    SxT  += r[0*8 + w];
                    SyT  += r[1*8 + w];
                    SxxT += r[2*8 + w];
                    SyyT += r[3*8 + w];
                    SxyT += r[4*8 + w];
                    SqT  += r[5*8 + w];
                }

                const float cx = center[b*3+0], cy = center[b*3+1], cz = center[b*3+2];

                float m0 = mask_mean[b*3+0] - cx;
                float m1 = mask_mean[b*3+1] - cy;
                float m2 = mask_mean[b*3+2] - cz;
                float cdist = sqrtf(m0*m0 + m1*m1 + m2*m2);

                const int sc = size_cls[b];
                float l  = mean_sizes[sc*3+0] + size_res[b*3+0];
                float ww = mean_sizes[sc*3+1] + size_res[b*3+1];

                const float PI_OVER_12 = 0.26179938779914943654f; // pi/12
                float heading = head_res[b] + (float)head_cls[b] * PI_OVER_12;
                float ch = cosf(heading), sh = sinf(heading);

                float hl = 0.5f * l, hw = 0.5f * ww;

                float vn = sqrtf(cx*cx + cy*cy);
                float inv_vn = 1.0f / vn;
                float p0 = -cy * inv_vn, p1 = cx * inv_vn;   // perpendicular dir
                float a0 =  cx * inv_vn, a1 = cy * inv_vn;   // v / |v|

                const float sxA[4] = {1.f, 1.f, -1.f, -1.f};
                const float syA[4] = {1.f, -1.f, -1.f, 1.f};
                float ppmax = -INFINITY, ppmin = INFINITY;
                float prmax = -INFINITY, prmin = INFINITY;
                #pragma unroll
                for (int k = 0; k < 4; k++) {
                    float X = ch * hl * sxA[k] - sh * hw * syA[k] + cx;
                    float Y = sh * hl * sxA[k] + ch * hw * syA[k] + cy;
                    float pp = X * p0 + Y * p1;
                    float pr = X * a0 + Y * a1;
                    ppmax = fmaxf(ppmax, pp); ppmin = fminf(ppmin, pp);
                    prmax = fmaxf(prmax, pr); prmin = fminf(prmin, pr);
                }
                float std_y_label  = (ppmax - ppmin) * 0.25f;
                float mean_y_label = (ppmax + ppmin) * 0.5f;
                float std_label    = (prmax - prmin) * 0.25f;
                float mean_label   = (prmax + prmin) * 0.5f;

                const float Nf = (float)Npts;
                const float invN = 1.0f / Nf;
                const float invNm1 = 1.0f / (Nf - 1.0f);

                float mean_pp = (p0 * SxT + p1 * SyT) * invN;
                float ss_pp   = p0*p0*SxxT + 2.f*p0*p1*SxyT + p1*p1*SyyT;
                float var_pp  = (ss_pp - Nf * mean_pp * mean_pp) * invNm1;
                float std_pp  = sqrtf(fmaxf(var_pp, 0.f));

                float mean_pr = (a0 * SxT + a1 * SyT) * invN;
                float ss_pr   = a0*a0*SxxT + 2.f*a0*a1*SxyT + a1*a1*SyyT;
                float var_pr  = (ss_pr - Nf * mean_pr * mean_pr) * invNm1;
                float std_pr  = sqrtf(fmaxf(var_pr, 0.f));

                float dnorm = sqrtf(SqT);

                float tval =
                      0.5f  * huber1(cdist)
                    + huber1(std_label  - std_pr)
                    + huber1(mean_label - mean_pr)
                    + 0.01f * huber1(dnorm)
                    + huber1(mean_y_label - mean_pp)
                    + huber1(std_y_label  - std_pp);

                g_partial[b] = tval;
            }
            // red[] is parity-double-buffered, so no second barrier needed here.
        }
    }

    // Block completion counting.
    __shared__ bool s_is_last;
    __syncthreads();
    if (t == 0) {
        __threadfence();
        unsigned prev = atomicAdd(&g_count, 1u);
        s_is_last = (prev == (unsigned)(nblocks - 1));
    }
    __syncthreads();

    // Last-arriving block performs the deterministic final sum (fixed order).
    if (s_is_last) {
        __shared__ float sh[THREADS];
        float s = 0.f;
        for (int i = t; i < Bn; i += THREADS)
            s += g_partial[i];
        sh[t] = s;
        __syncthreads();
        #pragma unroll
        for (int off = THREADS / 2; off > 0; off >>= 1) {
            if (t < off) sh[t] += sh[t + off];
            __syncthreads();
        }
        if (t == 0) {
            out[0] = 0.4f * sh[0] / (float)Bn;
            g_count = 0;   // reset for next graph replay
        }
    }
}

extern "C" void kernel_launch(void* const* d_in, const int* in_sizes, int n_in,
                              void* d_out, int out_size)
{
    const float* mask_mean  = (const float*)d_in[0];  // (B,3)
    const float* pc         = (const float*)d_in[1];  // (B,3,N)
    const float* xd         = (const float*)d_in[2];  // (B,3,N)
    const float* center     = (const float*)d_in[3];  // (B,3)
    const float* size_res   = (const float*)d_in[4];  // (B,3)
    const float* head_res   = (const float*)d_in[5];  // (B,)
    const float* mean_sizes = (const float*)d_in[6];  // (8,3)
    const int*   size_cls   = (const int*)d_in[7];    // (B,)
    const int*   head_cls   = (const int*)d_in[8];    // (B,)

    const int Bn   = in_sizes[0] / 3;
    const int Npts = in_sizes[1] / (3 * Bn);

    const int nblocks = (Bn + BPB - 1) / BPB;             // 256 for B=4096
    const size_t stageBytes = 20u * (size_t)Npts;         // 40 KB for N=2048
    const size_t smemBytes  = 512 + DEPTH * stageBytes;   // ~82.4 KB

    cudaFuncSetAttribute(loss_bulk_kernel,
                         cudaFuncAttributeMaxDynamicSharedMemorySize,
                         (int)smemBytes);

    loss_bulk_kernel<<<nblocks, THREADS, smemBytes>>>(
        mask_mean, pc, xd, center, size_res, head_res, mean_sizes,
        size_cls, head_cls, (float*)d_out, Npts, Bn, nblocks);
}

// round 12
// speedup vs baseline: 1.0776x; 1.0776x over previous
#include <cuda_runtime.h>
#include <cstdint>
#include <math.h>

#define THREADS 128   // 4 warps: wid0=pc(pair0) wid1=xd(pair0) wid2=pc(pair1) wid3=xd(pair1)

// Scratch (zero-initialized at module load; counter reset by last block each call).
__device__ float g_partial[8192];
__device__ unsigned int g_count;

__device__ __forceinline__ float huber1(float x) {
    float a = fabsf(x);
    float q = fminf(a, 1.0f);
    return 0.5f * q * q + (a - q);
}

__device__ __forceinline__ float4 ldcs4(const float4* p) {
    return __ldcs(p);
}

// Per-batch scalar epilogue. Pure function of its inputs -> deterministic
// regardless of which warp executes it.
__device__ void batch_epilogue(
    int b, float Sx, float Sy, float Sxx, float Syy, float Sxy, float Sq,
    int Npts,
    const float* __restrict__ mask_mean,
    const float* __restrict__ center,
    const float* __restrict__ size_res,
    const float* __restrict__ head_res,
    const float* __restrict__ mean_sizes,
    const int*   __restrict__ size_cls,
    const int*   __restrict__ head_cls)
{
    const float cx = center[b*3+0], cy = center[b*3+1], cz = center[b*3+2];

    float m0 = mask_mean[b*3+0] - cx;
    float m1 = mask_mean[b*3+1] - cy;
    float m2 = mask_mean[b*3+2] - cz;
    float cdist = sqrtf(m0*m0 + m1*m1 + m2*m2);

    const int sc = size_cls[b];
    float l  = mean_sizes[sc*3+0] + size_res[b*3+0];
    float ww = mean_sizes[sc*3+1] + size_res[b*3+1];

    const float PI_OVER_12 = 0.26179938779914943654f; // pi/12
    float heading = head_res[b] + (float)head_cls[b] * PI_OVER_12;
    float ch = cosf(heading), sh = sinf(heading);

    float hl = 0.5f * l, hw = 0.5f * ww;

    float vn = sqrtf(cx*cx + cy*cy);
    float inv_vn = 1.0f / vn;
    float p0 = -cy * inv_vn, p1 = cx * inv_vn;   // perpendicular dir
    float a0 =  cx * inv_vn, a1 = cy * inv_vn;   // v / |v|

    const float sxA[4] = {1.f, 1.f, -1.f, -1.f};
    const float syA[4] = {1.f, -1.f, -1.f, 1.f};
    float ppmax = -INFINITY, ppmin = INFINITY;
    float prmax = -INFINITY, prmin = INFINITY;
    #pragma unroll
    for (int k = 0; k < 4; k++) {
        float X = ch * hl * sxA[k] - sh * hw * syA[k] + cx;
        float Y = sh * hl * sxA[k] + ch * hw * syA[k] + cy;
        float pp = X * p0 + Y * p1;
        float pr = X * a0 + Y * a1;
        ppmax = fmaxf(ppmax, pp); ppmin = fminf(ppmin, pp);
        prmax = fmaxf(prmax, pr); prmin = fminf(prmin, pr);
    }
    float std_y_label  = (ppmax - ppmin) * 0.25f;
    float mean_y_label = (ppmax + ppmin) * 0.5f;
    float std_label    = (prmax - prmin) * 0.25f;
    float mean_label   = (prmax + prmin) * 0.5f;

    const float Nf = (float)Npts;
    const float invN = 1.0f / Nf;
    const float invNm1 = 1.0f / (Nf - 1.0f);

    float mean_pp = (p0 * Sx + p1 * Sy) * invN;
    float ss_pp   = p0*p0*Sxx + 2.f*p0*p1*Sxy + p1*p1*Syy;
    float var_pp  = (ss_pp - Nf * mean_pp * mean_pp) * invNm1;
    float std_pp  = sqrtf(fmaxf(var_pp, 0.f));

    float mean_pr = (a0 * Sx + a1 * Sy) * invN;
    float ss_pr   = a0*a0*Sxx + 2.f*a0*a1*Sxy + a1*a1*Syy;
    float var_pr  = (ss_pr - Nf * mean_pr * mean_pr) * invNm1;
    float std_pr  = sqrtf(fmaxf(var_pr, 0.f));

    float dnorm = sqrtf(Sq);

    float tval =
          0.5f  * huber1(cdist)
        + huber1(std_label  - std_pr)
        + huber1(mean_label - mean_pr)
        + 0.01f * huber1(dnorm)
        + huber1(mean_y_label - mean_pp)
        + huber1(std_y_label  - std_pp);

    g_partial[b] = tval;
}

__global__ __launch_bounds__(THREADS)
void loss_split_kernel(
    const float* __restrict__ mask_mean,     // (B,3)
    const float* __restrict__ pc,            // (B,3,N)
    const float* __restrict__ xd,            // (B,3,N)
    const float* __restrict__ center,        // (B,3)
    const float* __restrict__ size_res,      // (B,3)
    const float* __restrict__ head_res,      // (B,)
    const float* __restrict__ mean_sizes,    // (8,3)
    const int*   __restrict__ size_cls,      // (B,)
    const int*   __restrict__ head_cls,      // (B,)
    float* __restrict__ out,
    int Npts, int Bn, int nblocks)
{
    const int t    = threadIdx.x;
    const int lane = t & 31;
    const int wid  = t >> 5;
    const int n4   = Npts >> 2;          // float4s per row
    const unsigned full = 0xffffffffu;

    // Block-local handoff: s_mom[i][0..4] from pc warp, [5] from xd warp.
    __shared__ volatile float s_mom[4][6];
    __shared__ int  s_cnt[4];
    __shared__ bool s_is_last;
    if (t < 4) s_cnt[t] = 0;
    __syncthreads();

    const int b_base = blockIdx.x * 4;   // this block owns batches b_base..b_base+3
    const int half   = wid >> 1;         // pair index within block (0/1)
    const int role   = wid & 1;          // 0 = pc(xy moments), 1 = xd(Sq)
    const int bb     = b_base + 2 * half;

    if (bb < Bn) {
        if (role == 0) {
            // ---------- pc warp: 5 xy moments for batches bb, bb+1 ----------
            for (int k = 0; k < 2; k++) {
                const int b = bb + k;
                if (b >= Bn) break;
                const float4* __restrict__ px = (const float4*)(pc + (size_t)b * 3 * Npts);
                const float4* __restrict__ py = px + n4;

                float Sx = 0.f, Sy = 0.f, Sxx = 0.f, Syy = 0.f, Sxy = 0.f;

                if (n4 == 512) {
                    #pragma unroll
                    for (int g = 0; g < 2; g++) {
                        float4 xs[8], ys[8];
                        #pragma unroll
                        for (int u = 0; u < 8; u++)
                            xs[u] = ldcs4(&px[lane + (g * 8 + u) * 32]);
                        #pragma unroll
                        for (int u = 0; u < 8; u++)
                            ys[u] = ldcs4(&py[lane + (g * 8 + u) * 32]);
                        #pragma unroll
                        for (int u = 0; u < 8; u++) {
                            float4 x4 = xs[u], y4 = ys[u];
                            Sx  += (x4.x + x4.y) + (x4.z + x4.w);
                            Sy  += (y4.x + y4.y) + (y4.z + y4.w);
                            Sxx += x4.x*x4.x + x4.y*x4.y + x4.z*x4.z + x4.w*x4.w;
                            Syy += y4.x*y4.x + y4.y*y4.y + y4.z*y4.z + y4.w*y4.w;
                            Sxy += x4.x*y4.x + x4.y*y4.y + x4.z*y4.z + x4.w*y4.w;
                        }
                    }
                } else {
                    #pragma unroll 4
                    for (int j = lane; j < n4; j += 32) {
                        float4 x4 = ldcs4(&px[j]);
                        float4 y4 = ldcs4(&py[j]);
                        Sx  += (x4.x + x4.y) + (x4.z + x4.w);
                        Sy  += (y4.x + y4.y) + (y4.z + y4.w);
                        Sxx += x4.x*x4.x + x4.y*x4.y + x4.z*x4.z + x4.w*x4.w;
                        Syy += y4.x*y4.x + y4.y*y4.y + y4.z*y4.z + y4.w*y4.w;
                        Sxy += x4.x*y4.x + x4.y*y4.y + x4.z*y4.z + x4.w*y4.w;
                    }
                }

                #pragma unroll
                for (int off = 16; off > 0; off >>= 1) {
                    Sx  += __shfl_down_sync(full, Sx,  off);
                    Sy  += __shfl_down_sync(full, Sy,  off);
                    Sxx += __shfl_down_sync(full, Sxx, off);
                    Syy += __shfl_down_sync(full, Syy, off);
                    Sxy += __shfl_down_sync(full, Sxy, off);
                }

                if (lane == 0) {
                    const int idx = 2 * half + k;
                    s_mom[idx][0] = Sx;  s_mom[idx][1] = Sy;  s_mom[idx][2] = Sxx;
                    s_mom[idx][3] = Syy; s_mom[idx][4] = Sxy;
                    __threadfence_block();
                    int old = atomicAdd(&s_cnt[idx], 1);
                    if (old == 1) {
                        __threadfence_block();
                        batch_epilogue(b, Sx, Sy, Sxx, Syy, Sxy, s_mom[idx][5],
                                       Npts, mask_mean, center, size_res,
                                       head_res, mean_sizes, size_cls, head_cls);
                    }
                }
            }
        } else {
            // ---------- xd warp: Sq for batches bb, bb+1 (48 KB contiguous) ----------
            const float4* __restrict__ pd = (const float4*)(xd + (size_t)bb * 3 * Npts);
            const int nbatch = min(2, Bn - bb);
            float Sq0 = 0.f, Sq1 = 0.f;

            if (n4 == 512 && nbatch == 2) {
                // 6 groups of 16 front-batched loads; groups 0-2 -> Sq0, 3-5 -> Sq1.
                #pragma unroll
                for (int g = 0; g < 6; g++) {
                    float4 ds[16];
                    #pragma unroll
                    for (int u = 0; u < 16; u++)
                        ds[u] = ldcs4(&pd[lane + (g * 16 + u) * 32]);
                    float acc = 0.f;
                    #pragma unroll
                    for (int u = 0; u < 16; u++) {
                        float4 d = ds[u];
                        acc += (d.x*d.x + d.y*d.y) + (d.z*d.z + d.w*d.w);
                    }
                    if (g < 3) Sq0 += acc; else Sq1 += acc;
                }
            } else {
                const int m4 = 3 * n4;
                for (int k = 0; k < nbatch; k++) {
                    const float4* p = pd + (size_t)k * m4;
                    float acc = 0.f;
                    #pragma unroll 8
                    for (int j = lane; j < m4; j += 32) {
                        float4 d = ldcs4(&p[j]);
                        acc += (d.x*d.x + d.y*d.y) + (d.z*d.z + d.w*d.w);
                    }
                    if (k == 0) Sq0 = acc; else Sq1 = acc;
                }
            }

            #pragma unroll
            for (int off = 16; off > 0; off >>= 1) {
                Sq0 += __shfl_down_sync(full, Sq0, off);
                Sq1 += __shfl_down_sync(full, Sq1, off);
            }

            if (lane == 0) {
                for (int k = 0; k < nbatch; k++) {
                    const int idx = 2 * half + k;
                    s_mom[idx][5] = (k == 0) ? Sq0 : Sq1;
                }
                __threadfence_block();
                for (int k = 0; k < nbatch; k++) {
                    const int idx = 2 * half + k;
                    int old = atomicAdd(&s_cnt[idx], 1);
                    if (old == 1) {
                        __threadfence_block();
                        batch_epilogue(bb + k,
                                       s_mom[idx][0], s_mom[idx][1], s_mom[idx][2],
                                       s_mom[idx][3], s_mom[idx][4],
                                       (k == 0) ? Sq0 : Sq1,
                                       Npts, mask_mean, center, size_res,
                                       head_res, mean_sizes, size_cls, head_cls);
                    }
                }
            }
        }
    }

    // Block completion counting (standard threadfence-reduction pattern).
    __syncthreads();
    if (t == 0) {
        __threadfence();
        unsigned prev = atomicAdd(&g_count, 1u);
        s_is_last = (prev == (unsigned)(nblocks - 1));
    }
    __syncthreads();

    // Last-arriving block performs the deterministic final sum (fixed order).
    if (s_is_last) {
        __shared__ float sh[THREADS];
        float s = 0.f;
        for (int i = t; i < Bn; i += THREADS)
            s += g_partial[i];
        sh[t] = s;
        __syncthreads();
        #pragma unroll
        for (int off = THREADS / 2; off > 0; off >>= 1) {
            if (t < off) sh[t] += sh[t + off];
            __syncthreads();
        }
        if (t == 0) {
            out[0] = 0.4f * sh[0] / (float)Bn;
            g_count = 0;   // reset for next graph replay
        }
    }
}

extern "C" void kernel_launch(void* const* d_in, const int* in_sizes, int n_in,
                              void* d_out, int out_size)
{
    const float* mask_mean  = (const float*)d_in[0];  // (B,3)
    const float* pc         = (const float*)d_in[1];  // (B,3,N)
    const float* xd         = (const float*)d_in[2];  // (B,3,N)
    const float* center     = (const float*)d_in[3];  // (B,3)
    const float* size_res   = (const float*)d_in[4];  // (B,3)
    const float* head_res   = (const float*)d_in[5];  // (B,)
    const float* mean_sizes = (const float*)d_in[6];  // (8,3)
    const int*   size_cls   = (const int*)d_in[7];    // (B,)
    const int*   head_cls   = (const int*)d_in[8];    // (B,)

    const int Bn   = in_sizes[0] / 3;
    const int Npts = in_sizes[1] / (3 * Bn);

    // 4 batches per block (2 pc warps + 2 xd warps).
    const int nblocks = (Bn + 3) / 4;    // 1024 for B=4096

    loss_split_kernel<<<nblocks, THREADS>>>(mask_mean, pc, xd, center,
                                            size_res, head_res, mean_sizes,
                                            size_cls, head_cls,
                                            (float*)d_out, Npts, Bn, nblocks);
}